// round 12
// baseline (speedup 1.0000x reference)
#include <cuda_runtime.h>

// Problem constants (fixed by the reference)
#define SEQ_LEN   512
#define EMB       768
#define NLAB      9
#define FEAT      2354            // 3*768 + 50
#define WDIM      50
#define MAXW      16
#define NSPANS    32768
#define HALFK     384             // EMB/2 per k-half warp-group
#define TOKPB     2               // tokens per proj block (R10's best-measured)

// Packed fp32x2 FMA (Blackwell FFMA2 — only reachable via PTX f32x2)
#define FMA_F32X2(d, a, b, c) \
    asm("fma.rn.f32x2 %0, %1, %2, %3;" : "=l"(d) : "l"(a), "l"(b), "l"(c))

// Packed tables (allocation-free rule: __device__ globals)
// g_S[t*9+l] = (Ps[t][l], Pc[t][l])   Pc = exclusive prefix of Pa
// g_E[t*9+l] = (Pe[t][l], Pc[t][l])
// g_Wb[w*9+l] = (width_proj + bias, 1/w)
__device__ float2 g_S[SEQ_LEN * NLAB];
__device__ float2 g_E[SEQ_LEN * NLAB];
__device__ float  g_Pa[SEQ_LEN * NLAB];
__device__ float2 g_Wb[(MAXW + 1) * NLAB];

// ---------------------------------------------------------------------------
// K1: token projection, 2 tokens/block, k-split across 2 warp-groups,
// packed f32x2 FMAs. 256 blocks x 576 threads (4608 warps, ~7.8/SMSP).
// Warp: 3 dots x 2 tokens over its k-half; mainloop/warp: 6 iters x
// (2 LDS.64 + 3 LDG.64 + 6 FMA2). PDL-trigger releases K2 at store time.
// ---------------------------------------------------------------------------
__global__ void __launch_bounds__(576)
proj_kernel(const float* __restrict__ seq, const float* __restrict__ W) {
    __shared__ __align__(16) float srow[TOKPB][EMB];   // 6 KB
    __shared__ float spart[TOKPB][2 * 27];

    const int tid  = threadIdx.x;
    const int warp = tid >> 5;          // 0..17
    const int lane = tid & 31;
    const int t0   = blockIdx.x * TOKPB;

    // Stage 2 token rows (384 float4, one pass).
    if (tid < TOKPB * EMB / 4) {
        const float4 v = reinterpret_cast<const float4*>(seq + (size_t)t0 * EMB)[tid];
        reinterpret_cast<float4*>(&srow[0][0])[tid] = v;
    }
    __syncthreads();

    const int kh    = warp / 9;         // 0..1  k-half
    const int jg    = warp - 9 * kh;    // 0..8  dot-group
    const int kbase = kh * HALFK;

    const float* wbase[3];
    #pragma unroll
    for (int i = 0; i < 3; i++) {
        const int j = jg * 3 + i;
        const int l = j % 9, sl = j / 9;
        wbase[i] = W + (size_t)l * FEAT + sl * EMB + kbase;   // 8B-aligned
    }

    unsigned long long acc[TOKPB][3];
    #pragma unroll
    for (int t = 0; t < TOKPB; t++)
        #pragma unroll
        for (int i = 0; i < 3; i++) acc[t][i] = 0ull;

    #pragma unroll
    for (int it = 0; it < 6; it++) {
        const int k = it * 64 + lane * 2;
        unsigned long long sv[TOKPB];
        #pragma unroll
        for (int t = 0; t < TOKPB; t++)
            sv[t] = *reinterpret_cast<const unsigned long long*>(&srow[t][kbase + k]);
        #pragma unroll
        for (int i = 0; i < 3; i++) {
            const unsigned long long wv =
                __ldg(reinterpret_cast<const unsigned long long*>(wbase[i] + k));
            #pragma unroll
            for (int t = 0; t < TOKPB; t++)
                FMA_F32X2(acc[t][i], sv[t], wv, acc[t][i]);
        }
    }

    // Collapse f32x2 -> f32, shfl-reduce across lanes.
    float r[TOKPB][3];
    #pragma unroll
    for (int t = 0; t < TOKPB; t++)
        #pragma unroll
        for (int i = 0; i < 3; i++) {
            const float2 f = *reinterpret_cast<float2*>(&acc[t][i]);
            r[t][i] = f.x + f.y;
        }
    #pragma unroll
    for (int o = 16; o > 0; o >>= 1)
        #pragma unroll
        for (int t = 0; t < TOKPB; t++)
            #pragma unroll
            for (int i = 0; i < 3; i++)
                r[t][i] += __shfl_down_sync(0xffffffffu, r[t][i], o);

    if (lane == 0) {
        #pragma unroll
        for (int t = 0; t < TOKPB; t++)
            #pragma unroll
            for (int i = 0; i < 3; i++)
                spart[t][kh * 27 + jg * 3 + i] = r[t][i];
    }
    __syncthreads();

    // Combine k-halves; 54 threads write finals.
    if (tid < TOKPB * 27) {
        const int t = tid / 27;
        const int j = tid - t * 27;
        const float v = spart[t][j] + spart[t][27 + j];
        const int sl = j / 9, l = j - sl * 9;
        const int tok = t0 + t;
        if (sl == 0)
            reinterpret_cast<float*>(g_S)[(tok * NLAB + l) * 2] = v;
        else if (sl == 1)
            reinterpret_cast<float*>(g_E)[(tok * NLAB + l) * 2] = v;
        else
            g_Pa[tok * NLAB + l] = v;
    }
    __syncthreads();
    cudaTriggerProgrammaticLaunchCompletion();   // release K2 at last-store time
}

// ---------------------------------------------------------------------------
// K2 (PDL): width-table prologue (inputs only, overlaps K1) -> HW grid sync
// -> 9 parallel scans over 512 tokens (one block, 512 threads).
// ---------------------------------------------------------------------------
__global__ void __launch_bounds__(512)
scan_kernel(const float* __restrict__ wt,
            const float* __restrict__ W,
            const float* __restrict__ b) {
    __shared__ float tot[16][NLAB];
    __shared__ float carry[16][NLAB];

    const int tid  = threadIdx.x;
    const int lane = tid & 31;
    const int warp = tid >> 5;

    if (tid < (MAXW + 1) * NLAB) {
        const int w = tid / NLAB;
        const int l = tid % NLAB;
        const float* wrow = W + (size_t)l * FEAT + 3 * EMB;
        float a = __ldg(b + l);
        #pragma unroll
        for (int k = 0; k < WDIM; k++)
            a += __ldg(wt + w * WDIM + k) * __ldg(wrow + k);
        g_Wb[tid] = make_float2(a, 1.0f / (float)w);   // w=0 never read
    }

    cudaGridDependencySynchronize();      // HW wait for K1 (no polling, no fence)

    float x[NLAB], a[NLAB];
    #pragma unroll
    for (int l = 0; l < NLAB; l++) { x[l] = g_Pa[tid * NLAB + l]; a[l] = x[l]; }

    #pragma unroll
    for (int l = 0; l < NLAB; l++) {
        #pragma unroll
        for (int o = 1; o < 32; o <<= 1) {
            const float y = __shfl_up_sync(0xffffffffu, a[l], o);
            if (lane >= o) a[l] += y;
        }
    }
    if (lane == 31) {
        #pragma unroll
        for (int l = 0; l < NLAB; l++) tot[warp][l] = a[l];
    }
    __syncthreads();
    if (tid < NLAB) {
        float r = 0.f;
        #pragma unroll
        for (int w = 0; w < 16; w++) { carry[w][tid] = r; r += tot[w][tid]; }
    }
    __syncthreads();
    #pragma unroll
    for (int l = 0; l < NLAB; l++) {
        const float excl = a[l] - x[l] + carry[warp][l];   // Pc[tid]
        reinterpret_cast<float*>(g_S)[(tid * NLAB + l) * 2 + 1] = excl;
        reinterpret_cast<float*>(g_E)[(tid * NLAB + l) * 2 + 1] = excl;
    }
    __syncthreads();
    cudaTriggerProgrammaticLaunchCompletion();   // release K3 at last-store time
}

// ---------------------------------------------------------------------------
// K3 (PDL): assemble. Prologue loads indices (inputs only, overlaps K2),
// then HW sync, then table gathers + coalesced store.
// Block = 288 thr = 32 spans x 9 labels (exact cover).
// ---------------------------------------------------------------------------
__global__ void __launch_bounds__(288)
assemble_kernel(const int* __restrict__ st,
                const int* __restrict__ en,
                const int* __restrict__ wd,
                float* __restrict__ out) {
    const int tid  = threadIdx.x;
    const int sp_l = tid / NLAB;                 // 0..31
    const int l    = tid - sp_l * NLAB;          // 0..8
    const int span = blockIdx.x * 32 + sp_l;

    const int s = __ldg(st + span);              // prologue: inputs only
    const int e = __ldg(en + span);
    const int w = __ldg(wd + span);
    const int is = s * NLAB + l;
    const int ie = e * NLAB + l;
    const int iw = w * NLAB + l;

    cudaGridDependencySynchronize();             // HW wait for K2

    const float2 fs = g_S[is];
    const float2 fe = g_E[ie];
    const float2 fw = g_Wb[iw];
    out[blockIdx.x * 288 + tid] = fs.x + fe.x + (fe.y - fs.y) * fw.y + fw.x;
}

// ---------------------------------------------------------------------------
extern "C" void kernel_launch(void* const* d_in, const int* in_sizes, int n_in,
                              void* d_out, int out_size) {
    const float* seq = (const float*)d_in[0];   // [1,512,768]
    const int*   st  = (const int*)  d_in[1];   // [32768]
    const int*   en  = (const int*)  d_in[2];   // [32768]
    const int*   wd  = (const int*)  d_in[3];   // [32768]
    const float* wt  = (const float*)d_in[4];   // [17,50]
    const float* W   = (const float*)d_in[5];   // [9,2354]
    const float* b   = (const float*)d_in[6];   // [9]
    float* out = (float*)d_out;                 // [32768,9]

    proj_kernel<<<SEQ_LEN / TOKPB, 576>>>(seq, W);

    cudaLaunchAttribute at[1];
    at[0].id = cudaLaunchAttributeProgrammaticStreamSerialization;
    at[0].val.programmaticStreamSerializationAllowed = 1;

    {   // K2 with PDL
        cudaLaunchConfig_t cfg = {};
        cfg.gridDim = dim3(1, 1, 1);
        cfg.blockDim = dim3(512, 1, 1);
        cfg.stream = 0;
        cfg.attrs = at;
        cfg.numAttrs = 1;
        cudaLaunchKernelEx(&cfg, scan_kernel, wt, W, b);
    }
    {   // K3 with PDL
        cudaLaunchConfig_t cfg = {};
        cfg.gridDim = dim3(NSPANS / 32, 1, 1);
        cfg.blockDim = dim3(288, 1, 1);
        cfg.stream = 0;
        cfg.attrs = at;
        cfg.numAttrs = 1;
        cudaLaunchKernelEx(&cfg, assemble_kernel, st, en, wd, out);
    }
}

// round 13
// speedup vs baseline: 1.1214x; 1.1214x over previous
#include <cuda_runtime.h>

// Problem constants (fixed by the reference)
#define SEQ_LEN   512
#define EMB       768
#define NLAB      9
#define FEAT      2354            // 3*768 + 50
#define WDIM      50
#define MAXW      16
#define NSPANS    32768
#define HALFK     384             // EMB/2 per k-half warp-group

// Packed fp32x2 FMA (Blackwell FFMA2 — only reachable via PTX f32x2)
#define FMA_F32X2(d, a, b, c) \
    asm("fma.rn.f32x2 %0, %1, %2, %3;" : "=l"(d) : "l"(a), "l"(b), "l"(c))

// Packed tables (allocation-free rule: __device__ globals)
// g_S[t*9+l] = (Ps[t][l], Pc[t][l])   Pc = exclusive prefix of Pa
// g_E[t*9+l] = (Pe[t][l], Pc[t][l])
// g_Wb[w*9+l] = (width_proj + bias, 1/w)
__device__ float2 g_S[SEQ_LEN * NLAB];
__device__ float2 g_E[SEQ_LEN * NLAB];
__device__ float  g_Pa[SEQ_LEN * NLAB];
__device__ float2 g_Wb[(MAXW + 1) * NLAB];

// ---------------------------------------------------------------------------
// K1: token projection — R10's exact body (explicit scalar accumulators,
// which ptxas allocates at 56 regs with high MLP; the array form regressed
// to 32 regs / serialized loads) + PDL trigger appended.
// 256 blocks x 576 threads, 2 tokens/block, k-split across 2 warp-groups,
// packed f32x2 FMAs.
// ---------------------------------------------------------------------------
__global__ void __launch_bounds__(576)
proj_kernel(const float* __restrict__ seq, const float* __restrict__ W) {
    __shared__ __align__(16) float srow[2][EMB];      // 6 KB
    __shared__ float spart[2][2 * 27];                // [token][kh*27+j]

    const int tid  = threadIdx.x;
    const int warp = tid >> 5;          // 0..17
    const int lane = tid & 31;
    const int t0   = blockIdx.x * 2;

    // Stage both token rows (384 float4 total).
    if (tid < 2 * EMB / 4) {
        const float4 v = reinterpret_cast<const float4*>(seq + (size_t)t0 * EMB)[tid];
        reinterpret_cast<float4*>(&srow[0][0])[tid] = v;
    }
    __syncthreads();

    const int kh    = warp / 9;         // 0..1  k-half
    const int jg    = warp - 9 * kh;    // 0..8  dot-group
    const int kbase = kh * HALFK;

    const float* wbase[3];
    #pragma unroll
    for (int i = 0; i < 3; i++) {
        const int j = jg * 3 + i;
        const int l = j % 9, sl = j / 9;
        wbase[i] = W + (size_t)l * FEAT + sl * EMB + kbase;   // 8B-aligned
    }

    unsigned long long a0[3] = {0ull, 0ull, 0ull};
    unsigned long long a1[3] = {0ull, 0ull, 0ull};

    #pragma unroll
    for (int it = 0; it < 6; it++) {
        const int k = it * 64 + lane * 2;
        const unsigned long long s0 =
            *reinterpret_cast<const unsigned long long*>(&srow[0][kbase + k]);
        const unsigned long long s1 =
            *reinterpret_cast<const unsigned long long*>(&srow[1][kbase + k]);
        #pragma unroll
        for (int i = 0; i < 3; i++) {
            const unsigned long long wv =
                __ldg(reinterpret_cast<const unsigned long long*>(wbase[i] + k));
            FMA_F32X2(a0[i], s0, wv, a0[i]);
            FMA_F32X2(a1[i], s1, wv, a1[i]);
        }
    }

    // Collapse f32x2 -> f32, shfl-reduce across lanes.
    float r0[3], r1[3];
    #pragma unroll
    for (int i = 0; i < 3; i++) {
        const float2 f0 = *reinterpret_cast<float2*>(&a0[i]);
        const float2 f1 = *reinterpret_cast<float2*>(&a1[i]);
        r0[i] = f0.x + f0.y;
        r1[i] = f1.x + f1.y;
    }
    #pragma unroll
    for (int i = 0; i < 3; i++) {
        #pragma unroll
        for (int o = 16; o > 0; o >>= 1) {
            r0[i] += __shfl_down_sync(0xffffffffu, r0[i], o);
            r1[i] += __shfl_down_sync(0xffffffffu, r1[i], o);
        }
    }
    if (lane == 0) {
        #pragma unroll
        for (int i = 0; i < 3; i++) {
            spart[0][kh * 27 + jg * 3 + i] = r0[i];
            spart[1][kh * 27 + jg * 3 + i] = r1[i];
        }
    }
    __syncthreads();

    // Combine the two k-halves; 54 threads write finals.
    if (tid < 54) {
        const int t = tid / 27;             // 0..1
        const int j = tid - t * 27;         // 0..26
        const float v = spart[t][j] + spart[t][27 + j];
        const int sl = j / 9, l = j - sl * 9;
        const int tok = t0 + t;
        if (sl == 0)
            reinterpret_cast<float*>(g_S)[(tok * NLAB + l) * 2] = v;
        else if (sl == 1)
            reinterpret_cast<float*>(g_E)[(tok * NLAB + l) * 2] = v;
        else
            g_Pa[tok * NLAB + l] = v;
    }
    __syncthreads();
    cudaTriggerProgrammaticLaunchCompletion();   // release K2 at last-store time
}

// ---------------------------------------------------------------------------
// K2 (PDL): width-table prologue (inputs only, overlaps K1) -> HW grid sync
// -> 9 parallel scans over 512 tokens (one block, 512 threads).
// ---------------------------------------------------------------------------
__global__ void __launch_bounds__(512)
scan_kernel(const float* __restrict__ wt,
            const float* __restrict__ W,
            const float* __restrict__ b) {
    __shared__ float tot[16][NLAB];
    __shared__ float carry[16][NLAB];

    const int tid  = threadIdx.x;
    const int lane = tid & 31;
    const int warp = tid >> 5;

    if (tid < (MAXW + 1) * NLAB) {
        const int w = tid / NLAB;
        const int l = tid % NLAB;
        const float* wrow = W + (size_t)l * FEAT + 3 * EMB;
        float a = __ldg(b + l);
        #pragma unroll
        for (int k = 0; k < WDIM; k++)
            a += __ldg(wt + w * WDIM + k) * __ldg(wrow + k);
        g_Wb[tid] = make_float2(a, 1.0f / (float)w);   // w=0 never read
    }

    cudaGridDependencySynchronize();      // HW wait for K1 (no polling, no fence)

    float x[NLAB], a[NLAB];
    #pragma unroll
    for (int l = 0; l < NLAB; l++) { x[l] = g_Pa[tid * NLAB + l]; a[l] = x[l]; }

    #pragma unroll
    for (int l = 0; l < NLAB; l++) {
        #pragma unroll
        for (int o = 1; o < 32; o <<= 1) {
            const float y = __shfl_up_sync(0xffffffffu, a[l], o);
            if (lane >= o) a[l] += y;
        }
    }
    if (lane == 31) {
        #pragma unroll
        for (int l = 0; l < NLAB; l++) tot[warp][l] = a[l];
    }
    __syncthreads();
    if (tid < NLAB) {
        float r = 0.f;
        #pragma unroll
        for (int w = 0; w < 16; w++) { carry[w][tid] = r; r += tot[w][tid]; }
    }
    __syncthreads();
    #pragma unroll
    for (int l = 0; l < NLAB; l++) {
        const float excl = a[l] - x[l] + carry[warp][l];   // Pc[tid]
        reinterpret_cast<float*>(g_S)[(tid * NLAB + l) * 2 + 1] = excl;
        reinterpret_cast<float*>(g_E)[(tid * NLAB + l) * 2 + 1] = excl;
    }
    __syncthreads();
    cudaTriggerProgrammaticLaunchCompletion();   // release K3 at last-store time
}

// ---------------------------------------------------------------------------
// K3 (PDL): assemble. Prologue loads indices (inputs only, overlaps K2),
// then HW sync, then table gathers + coalesced store.
// Block = 288 thr = 32 spans x 9 labels (exact cover).
// ---------------------------------------------------------------------------
__global__ void __launch_bounds__(288)
assemble_kernel(const int* __restrict__ st,
                const int* __restrict__ en,
                const int* __restrict__ wd,
                float* __restrict__ out) {
    const int tid  = threadIdx.x;
    const int sp_l = tid / NLAB;                 // 0..31
    const int l    = tid - sp_l * NLAB;          // 0..8
    const int span = blockIdx.x * 32 + sp_l;

    const int s = __ldg(st + span);              // prologue: inputs only
    const int e = __ldg(en + span);
    const int w = __ldg(wd + span);
    const int is = s * NLAB + l;
    const int ie = e * NLAB + l;
    const int iw = w * NLAB + l;

    cudaGridDependencySynchronize();             // HW wait for K2

    const float2 fs = g_S[is];
    const float2 fe = g_E[ie];
    const float2 fw = g_Wb[iw];
    out[blockIdx.x * 288 + tid] = fs.x + fe.x + (fe.y - fs.y) * fw.y + fw.x;
}

// ---------------------------------------------------------------------------
extern "C" void kernel_launch(void* const* d_in, const int* in_sizes, int n_in,
                              void* d_out, int out_size) {
    const float* seq = (const float*)d_in[0];   // [1,512,768]
    const int*   st  = (const int*)  d_in[1];   // [32768]
    const int*   en  = (const int*)  d_in[2];   // [32768]
    const int*   wd  = (const int*)  d_in[3];   // [32768]
    const float* wt  = (const float*)d_in[4];   // [17,50]
    const float* W   = (const float*)d_in[5];   // [9,2354]
    const float* b   = (const float*)d_in[6];   // [9]
    float* out = (float*)d_out;                 // [32768,9]

    proj_kernel<<<SEQ_LEN / 2, 576>>>(seq, W);

    cudaLaunchAttribute at[1];
    at[0].id = cudaLaunchAttributeProgrammaticStreamSerialization;
    at[0].val.programmaticStreamSerializationAllowed = 1;

    {   // K2 with PDL
        cudaLaunchConfig_t cfg = {};
        cfg.gridDim = dim3(1, 1, 1);
        cfg.blockDim = dim3(512, 1, 1);
        cfg.stream = 0;
        cfg.attrs = at;
        cfg.numAttrs = 1;
        cudaLaunchKernelEx(&cfg, scan_kernel, wt, W, b);
    }
    {   // K3 with PDL
        cudaLaunchConfig_t cfg = {};
        cfg.gridDim = dim3(NSPANS / 32, 1, 1);
        cfg.blockDim = dim3(288, 1, 1);
        cfg.stream = 0;
        cfg.attrs = at;
        cfg.numAttrs = 1;
        cudaLaunchKernelEx(&cfg, assemble_kernel, st, en, wd, out);
    }
}